// round 14
// baseline (speedup 1.0000x reference)
#include <cuda_runtime.h>
#include <cstdint>
#include <math.h>

#define H_IN    24
#define F       50
#define FP      52      // padded feature stride (52*4=208 bytes, 16B aligned)
#define DH      100
#define DT      0.0625f
#define SQDT    0.25f
#define SIG     5.0f

// ---------------- packed f32x2 helpers (Blackwell FFMA2 path) ----------------
__device__ __forceinline__ uint64_t pack2(float lo, float hi) {
    uint64_t r;
    asm("mov.b64 %0, {%1, %2};" : "=l"(r) : "f"(lo), "f"(hi));
    return r;
}
__device__ __forceinline__ float2 unpack2(uint64_t v) {
    float2 r;
    asm("mov.b64 {%0, %1}, %2;" : "=f"(r.x), "=f"(r.y) : "l"(v));
    return r;
}
__device__ __forceinline__ void ffma2(uint64_t& d, uint64_t a, uint64_t b) {
    asm("fma.rn.f32x2 %0, %1, %2, %0;" : "+l"(d) : "l"(a), "l"(b));
}
__device__ __forceinline__ uint64_t add2(uint64_t a, uint64_t b) {
    uint64_t r;
    asm("add.rn.f32x2 %0, %1, %2;" : "=l"(r) : "l"(a), "l"(b));
    return r;
}

__device__ __forceinline__ float fast_sqrtf(float x) {
    float r;
    asm("sqrt.approx.f32 %0, %1;" : "=f"(r) : "f"(x));
    return r;
}

// ---------------- Threefry-2x32 (matches JAX) ----------------
__device__ __forceinline__ void tf_round(uint32_t& x0, uint32_t& x1, int r) {
    x0 += x1;
    x1 = __funnelshift_l(x1, x1, r);
    x1 ^= x0;
}

// Full threefry (used for fold_in key derivation)
__device__ __forceinline__ void threefry2x32(uint32_t k0, uint32_t k1,
                                             uint32_t c0, uint32_t c1,
                                             uint32_t& o0, uint32_t& o1) {
    uint32_t k2 = k0 ^ k1 ^ 0x1BD11BDAu;
    uint32_t x0 = c0 + k0, x1 = c1 + k1;
    tf_round(x0,x1,13); tf_round(x0,x1,15); tf_round(x0,x1,26); tf_round(x0,x1, 6);
    x0 += k1; x1 += k2 + 1u;
    tf_round(x0,x1,17); tf_round(x0,x1,29); tf_round(x0,x1,16); tf_round(x0,x1,24);
    x0 += k2; x1 += k0 + 2u;
    tf_round(x0,x1,13); tf_round(x0,x1,15); tf_round(x0,x1,26); tf_round(x0,x1, 6);
    x0 += k0; x1 += k1 + 3u;
    tf_round(x0,x1,17); tf_round(x0,x1,29); tf_round(x0,x1,16); tf_round(x0,x1,24);
    x0 += k1; x1 += k2 + 4u;
    tf_round(x0,x1,13); tf_round(x0,x1,15); tf_round(x0,x1,26); tf_round(x0,x1, 6);
    o0 = x0 + k2;
    o1 = x1 + k0 + 5u;
}

// Partitionable-mode random bits for sample index j (< 2^32):
// counter = (0, j); bits = out0 ^ out1. c0 = 0 folded in (x0 starts at k0).
__device__ __forceinline__ uint32_t tf_bits(uint32_t k0, uint32_t k1, uint32_t k2,
                                            uint32_t kb1, uint32_t kb2, uint32_t kb3,
                                            uint32_t kb4, uint32_t kb5,
                                            uint32_t x1_init) {
    uint32_t x0 = k0;
    uint32_t x1 = x1_init;                       // (cbase + f) + k1
    tf_round(x0,x1,13); tf_round(x0,x1,15); tf_round(x0,x1,26); tf_round(x0,x1, 6);
    x0 += k1; x1 += kb1;
    tf_round(x0,x1,17); tf_round(x0,x1,29); tf_round(x0,x1,16); tf_round(x0,x1,24);
    x0 += k2; x1 += kb2;
    tf_round(x0,x1,13); tf_round(x0,x1,15); tf_round(x0,x1,26); tf_round(x0,x1, 6);
    x0 += k0; x1 += kb3;
    tf_round(x0,x1,17); tf_round(x0,x1,29); tf_round(x0,x1,16); tf_round(x0,x1,24);
    x0 += k1; x1 += kb4;
    tf_round(x0,x1,13); tf_round(x0,x1,15); tf_round(x0,x1,26); tf_round(x0,x1, 6);
    return (x0 + k2) ^ (x1 + kb5);
}

// bits -> erfinv(u)*u normal (unscaled by sqrt2; folded into coef outside),
// BRANCHLESS. w = -log((1-u)(1+u)); JAX lower clamp is a no-op (removed).
__device__ __forceinline__ float bits_to_normal_noscale(uint32_t bits) {
    float r = __uint_as_float(0x3f800000u | (bits >> 9)) - 1.0f;   // [0,1)
    float u = fmaf(r, 2.0f, -0.99999994f);
    float w = -__logf((1.0f - u) * (1.0f + u));
    float wa = w - 2.5f;
    float pa = 2.81022636e-08f;
    pa = fmaf(pa, wa, 3.43273939e-07f);
    pa = fmaf(pa, wa, -3.5233877e-06f);
    pa = fmaf(pa, wa, -4.39150654e-06f);
    pa = fmaf(pa, wa, 0.00021858087f);
    pa = fmaf(pa, wa, -0.00125372503f);
    pa = fmaf(pa, wa, -0.00417768164f);
    pa = fmaf(pa, wa, 0.246640727f);
    pa = fmaf(pa, wa, 1.50140941f);
    float wb = fast_sqrtf(w) - 3.0f;
    float pb = -0.000200214257f;
    pb = fmaf(pb, wb, 0.000100950558f);
    pb = fmaf(pb, wb, 0.00134934322f);
    pb = fmaf(pb, wb, -0.00367342844f);
    pb = fmaf(pb, wb, 0.00573950773f);
    pb = fmaf(pb, wb, -0.0076224613f);
    pb = fmaf(pb, wb, 0.00943887047f);
    pb = fmaf(pb, wb, 1.00167406f);
    pb = fmaf(pb, wb, 2.83297682f);
    float p = (w < 5.0f) ? pa : pb;     // FSEL, no branch
    return p * u;
}

__global__ void __launch_bounds__(128, 3)
sde_kernel(const float* __restrict__ x,
           const float* __restrict__ W_down,  const float* __restrict__ b_down,
           const float* __restrict__ W_drift, const float* __restrict__ b_drift,
           const float* __restrict__ W_diff1, const float* __restrict__ b_diff1,
           const float* __restrict__ W_diff2, const float* __restrict__ b_diff2,
           const float* __restrict__ W_fc,    const float* __restrict__ b_fc,
           float* __restrict__ out, int N)
{
    __shared__ __align__(16) float sWdown[H_IN * FP];
    __shared__ __align__(16) float sWd[F * FP];    // W_drift rows: [j][k]
    __shared__ __align__(16) float sW1T[DH * FP];  // transposed diff1: [m][j]
    __shared__ __align__(16) float sW2[DH];
    __shared__ __align__(16) float sB1[DH];
    __shared__ __align__(16) float sBdown[FP];
    __shared__ __align__(16) float sBdrift[FP];
    __shared__ __align__(16) float sWfc[2 * F];    // [k*2+c]
    __shared__ uint32_t sK0[64], sK1[64];
    extern __shared__ unsigned long long oSmem[];  // [25][128] packed o pairs

    const int tid = threadIdx.x;

    for (int idx = tid; idx < H_IN * FP; idx += blockDim.x) {
        int h = idx / FP, k = idx - h * FP;
        sWdown[idx] = (k < F) ? W_down[h * F + k] : 0.0f;
    }
    for (int idx = tid; idx < F * FP; idx += blockDim.x) {
        int j = idx / FP, k = idx - j * FP;
        sWd[idx] = (k < F) ? W_drift[j * F + k] : 0.0f;
    }
    for (int idx = tid; idx < DH * FP; idx += blockDim.x) {
        int m = idx / FP, j = idx - m * FP;
        sW1T[idx] = (j < F) ? W_diff1[j * DH + m] : 0.0f;
    }
    for (int idx = tid; idx < DH; idx += blockDim.x) {
        sW2[idx] = W_diff2[idx];
        sB1[idx] = b_diff1[idx];
        sWfc[idx] = W_fc[idx];
    }
    for (int idx = tid; idx < FP; idx += blockDim.x) {
        sBdown[idx]  = (idx < F) ? b_down[idx]  : 0.0f;
        sBdrift[idx] = (idx < F) ? b_drift[idx] : 0.0f;
    }
    // per-step fold_in keys: threefry((0,42), (0,i))
    if (tid < 64) {
        uint32_t a, b;
        threefry2x32(0u, 42u, 0u, (uint32_t)tid, a, b);
        sK0[tid] = a; sK1[tid] = b;
    }
    __syncthreads();

    const uint32_t t = blockIdx.x * blockDim.x + tid;   // one token per thread
    if (t >= (uint32_t)N) return;
    const uint32_t cbase = t * 50u;                     // flattened sample base

    float coef;
    uint64_t accpA[26], accpB[26];
    {
        // downsample into temporary packed op
        uint64_t op[26];
        {
            const ulonglong2* bb = reinterpret_cast<const ulonglong2*>(sBdown);
            #pragma unroll
            for (int q = 0; q < 13; q++) {
                ulonglong2 b2 = bb[q];
                op[2*q] = b2.x; op[2*q+1] = b2.y;
            }
        }
        const float* xp = x + (size_t)t * H_IN;
        #pragma unroll
        for (int h = 0; h < H_IN; h++) {
            float xv = __ldg(xp + h);
            uint64_t xvv = pack2(xv, xv);
            const ulonglong2* wrow = reinterpret_cast<const ulonglong2*>(&sWdown[h * FP]);
            #pragma unroll
            for (int q = 0; q < 13; q++) {
                ulonglong2 w = wrow[q];
                ffma2(op[2*q],   xvv, w.x);
                ffma2(op[2*q+1], xvv, w.y);
            }
        }

        // diffusion net at t=0
        float ds = __ldg(b_diff2);
        #pragma unroll 4
        for (int m = 0; m < DH; m++) {
            uint64_t sp = pack2(sB1[m], 0.0f);
            const ulonglong2* wrow = reinterpret_cast<const ulonglong2*>(&sW1T[m * FP]);
            #pragma unroll
            for (int q = 0; q < 13; q++) {
                ulonglong2 w = wrow[q];
                ffma2(sp, op[2*q],   w.x);
                ffma2(sp, op[2*q+1], w.y);
            }
            float2 sv = unpack2(sp);
            float s = sv.x + sv.y;
            ds = fmaf(fmaxf(s, 0.0f), sW2[m], ds);
        }
        coef = SIG * (1.0f / (1.0f + expf(-ds))) * SQDT;

        // store o to SMEM ([q][tid] layout, conflict-free 64-bit)
        #pragma unroll
        for (int q = 0; q < 25; q++) oSmem[q * 128 + tid] = op[q];

        // prologue: accpA = b_drift + W_drift applied to o (rank-1 form)
        {
            const ulonglong2* bb = reinterpret_cast<const ulonglong2*>(sBdrift);
            #pragma unroll
            for (int q = 0; q < 13; q++) {
                ulonglong2 b2 = bb[q];
                accpA[2*q] = b2.x; accpA[2*q+1] = b2.y;
            }
        }
        #pragma unroll 5
        for (int jq = 0; jq < 25; jq++) {
            float2 ov = unpack2(op[jq]);
            uint64_t o0 = pack2(ov.x, ov.x);
            uint64_t o1 = pack2(ov.y, ov.y);
            const ulonglong2* w0 = reinterpret_cast<const ulonglong2*>(&sWd[(2*jq)   * FP]);
            const ulonglong2* w1 = reinterpret_cast<const ulonglong2*>(&sWd[(2*jq+1) * FP]);
            #pragma unroll
            for (int q = 0; q < 13; q++) {
                ulonglong2 wa = w0[q];
                ulonglong2 wb = w1[q];
                ffma2(accpA[2*q],   o0, wa.x);
                ffma2(accpA[2*q+1], o0, wa.y);
                ffma2(accpA[2*q],   o1, wb.x);
                ffma2(accpA[2*q+1], o1, wb.y);
            }
        }
    }

    const uint64_t DT2 = pack2(DT, DT);
    const float coefs = coef * 1.41421356f;        // fold sqrt(2)
    const uint64_t coef2 = pack2(coefs, coefs);

    // fused step: noise + delta + rank-1 scatter, accpCur -> accpNext.
    // accpNext starts as a COPY of accpCur (accp already contains b + W·o;
    // the R13 bug was re-initializing with the bias, dropping W·o).
    auto run_step = [&](int i, uint64_t* accpCur, uint64_t* accpNext) {
        const uint32_t fk0 = sK0[i], fk1 = sK1[i];
        const uint32_t fk2 = fk0 ^ fk1 ^ 0x1BD11BDAu;
        const uint32_t kb1 = fk2 + 1u, kb2 = fk0 + 2u, kb3 = fk1 + 3u,
                       kb4 = fk2 + 4u, kb5 = fk0 + 5u;
        const uint32_t x1base = cbase + fk1;

        #pragma unroll
        for (int q = 0; q < 26; q++) accpNext[q] = accpCur[q];

        #pragma unroll 5
        for (int q = 0; q < 25; q++) {
            // noise (alu-heavy, independent chains)
            uint32_t b0 = tf_bits(fk0, fk1, fk2, kb1, kb2, kb3, kb4, kb5,
                                  x1base + (uint32_t)(2*q));
            uint32_t b1 = tf_bits(fk0, fk1, fk2, kb1, kb2, kb3, kb4, kb5,
                                  x1base + (uint32_t)(2*q) + 1u);
            float z0 = bits_to_normal_noscale(b0);
            float z1 = bits_to_normal_noscale(b1);

            // delta: d = relu(accpCur[q])*DT + coef*z  (reads step-start accp)
            float2 a = unpack2(accpCur[q]);
            uint64_t dp = pack2(0.0f, 0.0f);
            uint64_t ap = pack2(fmaxf(a.x, 0.0f), fmaxf(a.y, 0.0f));
            ffma2(dp, ap, DT2);
            uint64_t zp = pack2(z0, z1);
            ffma2(dp, zp, coef2);

            // o state update in SMEM
            uint64_t ov = oSmem[q * 128 + tid];
            oSmem[q * 128 + tid] = add2(ov, dp);

            // rank-1 scatter: accpNext += W_drift rows (2q, 2q+1) * d
            float2 dv = unpack2(dp);
            uint64_t d0 = pack2(dv.x, dv.x);
            uint64_t d1 = pack2(dv.y, dv.y);
            const ulonglong2* w0 = reinterpret_cast<const ulonglong2*>(&sWd[(2*q)   * FP]);
            const ulonglong2* w1 = reinterpret_cast<const ulonglong2*>(&sWd[(2*q+1) * FP]);
            #pragma unroll
            for (int kk = 0; kk < 13; kk++) {
                ulonglong2 wa = w0[kk];
                ulonglong2 wb = w1[kk];
                ffma2(accpNext[2*kk],   d0, wa.x);
                ffma2(accpNext[2*kk+1], d0, wa.y);
                ffma2(accpNext[2*kk],   d1, wb.x);
                ffma2(accpNext[2*kk+1], d1, wb.y);
            }
        }
    };

    // 64 steps, ping-pong between accpA and accpB
    for (int i = 0; i < 64; i += 2) {
        run_step(i,     accpA, accpB);
        run_step(i + 1, accpB, accpA);
    }

    // ---- head: final = relu(o) @ W_fc + b_fc; mu, softplus(sigma)+1e-3 ----
    float mu = __ldg(b_fc + 0);
    float sg = __ldg(b_fc + 1);
    #pragma unroll
    for (int q = 0; q < 25; q++) {
        float2 ov = unpack2(oSmem[q * 128 + tid]);
        float r0 = fmaxf(ov.x, 0.0f);
        float r1 = fmaxf(ov.y, 0.0f);
        mu = fmaf(r0, sWfc[4*q],     mu);
        sg = fmaf(r0, sWfc[4*q + 1], sg);
        mu = fmaf(r1, sWfc[4*q + 2], mu);
        sg = fmaf(r1, sWfc[4*q + 3], sg);
    }
    float sigma = fmaxf(sg, 0.0f) + log1pf(expf(-fabsf(sg))) + 0.001f;

    out[t] = mu;
    out[(size_t)N + t] = sigma;
}

extern "C" void kernel_launch(void* const* d_in, const int* in_sizes, int n_in,
                              void* d_out, int out_size)
{
    const float* x       = (const float*)d_in[0];
    const float* W_down  = (const float*)d_in[1];
    const float* b_down  = (const float*)d_in[2];
    const float* W_drift = (const float*)d_in[3];
    const float* b_drift = (const float*)d_in[4];
    const float* W_diff1 = (const float*)d_in[5];
    const float* b_diff1 = (const float*)d_in[6];
    const float* W_diff2 = (const float*)d_in[7];
    const float* b_diff2 = (const float*)d_in[8];
    const float* W_fc    = (const float*)d_in[9];
    const float* b_fc    = (const float*)d_in[10];

    int N = in_sizes[0] / H_IN;          // number of tokens (B*L)
    int threads = 128;
    int blocks = (N + threads - 1) / threads;
    size_t dyn_smem = 25 * 128 * sizeof(unsigned long long);   // 25.6 KB

    // Opt in to static(38.3KB) + dynamic(25.6KB) > 48KB default. Not a stream
    // op: legal during graph capture, idempotent, no allocation.
    cudaFuncSetAttribute(sde_kernel, cudaFuncAttributeMaxDynamicSharedMemorySize,
                         (int)dyn_smem);

    sde_kernel<<<blocks, threads, dyn_smem>>>(x, W_down, b_down, W_drift, b_drift,
                                              W_diff1, b_diff1, W_diff2, b_diff2,
                                              W_fc, b_fc, (float*)d_out, N);
}

// round 16
// speedup vs baseline: 1.5433x; 1.5433x over previous
#include <cuda_runtime.h>
#include <cstdint>
#include <math.h>

#define H_IN    24
#define F       50
#define FP      52      // padded feature stride (52*4=208 bytes, 16B aligned)
#define DH      100
#define DT      0.0625f
#define SQDT    0.25f
#define SIG     5.0f

// ---------------- packed f32x2 helpers (Blackwell FFMA2 path) ----------------
__device__ __forceinline__ uint64_t pack2(float lo, float hi) {
    uint64_t r;
    asm("mov.b64 %0, {%1, %2};" : "=l"(r) : "f"(lo), "f"(hi));
    return r;
}
__device__ __forceinline__ float2 unpack2(uint64_t v) {
    float2 r;
    asm("mov.b64 {%0, %1}, %2;" : "=f"(r.x), "=f"(r.y) : "l"(v));
    return r;
}
__device__ __forceinline__ void ffma2(uint64_t& d, uint64_t a, uint64_t b) {
    asm("fma.rn.f32x2 %0, %1, %2, %0;" : "+l"(d) : "l"(a), "l"(b));
}

__device__ __forceinline__ float fast_sqrtf(float x) {
    float r;
    asm("sqrt.approx.f32 %0, %1;" : "=f"(r) : "f"(x));
    return r;
}

// ---------------- Threefry-2x32 (matches JAX) ----------------
__device__ __forceinline__ void tf_round(uint32_t& x0, uint32_t& x1, int r) {
    x0 += x1;
    x1 = __funnelshift_l(x1, x1, r);
    x1 ^= x0;
}

// Full threefry (used for fold_in key derivation)
__device__ __forceinline__ void threefry2x32(uint32_t k0, uint32_t k1,
                                             uint32_t c0, uint32_t c1,
                                             uint32_t& o0, uint32_t& o1) {
    uint32_t k2 = k0 ^ k1 ^ 0x1BD11BDAu;
    uint32_t x0 = c0 + k0, x1 = c1 + k1;
    tf_round(x0,x1,13); tf_round(x0,x1,15); tf_round(x0,x1,26); tf_round(x0,x1, 6);
    x0 += k1; x1 += k2 + 1u;
    tf_round(x0,x1,17); tf_round(x0,x1,29); tf_round(x0,x1,16); tf_round(x0,x1,24);
    x0 += k2; x1 += k0 + 2u;
    tf_round(x0,x1,13); tf_round(x0,x1,15); tf_round(x0,x1,26); tf_round(x0,x1, 6);
    x0 += k0; x1 += k1 + 3u;
    tf_round(x0,x1,17); tf_round(x0,x1,29); tf_round(x0,x1,16); tf_round(x0,x1,24);
    x0 += k1; x1 += k2 + 4u;
    tf_round(x0,x1,13); tf_round(x0,x1,15); tf_round(x0,x1,26); tf_round(x0,x1, 6);
    o0 = x0 + k2;
    o1 = x1 + k0 + 5u;
}

// Partitionable-mode random bits for sample index j (< 2^32):
// counter = (0, j); bits = out0 ^ out1. c0 = 0 folded in (x0 starts at k0).
// kb1..kb5 hoisted per-step key-injection constants. Pure alu-pipe version.
__device__ __forceinline__ uint32_t tf_bits(uint32_t k0, uint32_t k1, uint32_t k2,
                                            uint32_t kb1, uint32_t kb2, uint32_t kb3,
                                            uint32_t kb4, uint32_t kb5,
                                            uint32_t x1_init) {
    uint32_t x0 = k0;
    uint32_t x1 = x1_init;                       // (cbase + f) + k1
    tf_round(x0,x1,13); tf_round(x0,x1,15); tf_round(x0,x1,26); tf_round(x0,x1, 6);
    x0 += k1; x1 += kb1;
    tf_round(x0,x1,17); tf_round(x0,x1,29); tf_round(x0,x1,16); tf_round(x0,x1,24);
    x0 += k2; x1 += kb2;
    tf_round(x0,x1,13); tf_round(x0,x1,15); tf_round(x0,x1,26); tf_round(x0,x1, 6);
    x0 += k0; x1 += kb3;
    tf_round(x0,x1,17); tf_round(x0,x1,29); tf_round(x0,x1,16); tf_round(x0,x1,24);
    x0 += k1; x1 += kb4;
    tf_round(x0,x1,13); tf_round(x0,x1,15); tf_round(x0,x1,26); tf_round(x0,x1, 6);
    return (x0 + k2) ^ (x1 + kb5);
}

// bits -> erfinv(u)*u normal (unscaled by sqrt2; folded into coef outside),
// BRANCHLESS. Validated R11 formulation: r exact in [0,1), u by single-rounded
// fma (guarantees u >= -0.99999994 > -1, so log arg > 0 — the R15 [2,4) trick
// failed because 2.99999994f is not representable and rounded to 3.0f).
__device__ __forceinline__ float bits_to_normal_noscale(uint32_t bits) {
    float r = __uint_as_float(0x3f800000u | (bits >> 9)) - 1.0f;   // [0,1)
    float u = fmaf(r, 2.0f, -0.99999994f);
    float w = -__logf((1.0f - u) * (1.0f + u));
    float wa = w - 2.5f;
    float pa = 2.81022636e-08f;
    pa = fmaf(pa, wa, 3.43273939e-07f);
    pa = fmaf(pa, wa, -3.5233877e-06f);
    pa = fmaf(pa, wa, -4.39150654e-06f);
    pa = fmaf(pa, wa, 0.00021858087f);
    pa = fmaf(pa, wa, -0.00125372503f);
    pa = fmaf(pa, wa, -0.00417768164f);
    pa = fmaf(pa, wa, 0.246640727f);
    pa = fmaf(pa, wa, 1.50140941f);
    float wb = fast_sqrtf(w) - 3.0f;
    float pb = -0.000200214257f;
    pb = fmaf(pb, wb, 0.000100950558f);
    pb = fmaf(pb, wb, 0.00134934322f);
    pb = fmaf(pb, wb, -0.00367342844f);
    pb = fmaf(pb, wb, 0.00573950773f);
    pb = fmaf(pb, wb, -0.0076224613f);
    pb = fmaf(pb, wb, 0.00943887047f);
    pb = fmaf(pb, wb, 1.00167406f);
    pb = fmaf(pb, wb, 2.83297682f);
    float p = (w < 5.0f) ? pa : pb;     // FSEL, no branch
    return p * u;
}

__global__ void __launch_bounds__(128, 3)
sde_kernel(const float* __restrict__ x,
           const float* __restrict__ W_down,  const float* __restrict__ b_down,
           const float* __restrict__ W_drift, const float* __restrict__ b_drift,
           const float* __restrict__ W_diff1, const float* __restrict__ b_diff1,
           const float* __restrict__ W_diff2, const float* __restrict__ b_diff2,
           const float* __restrict__ W_fc,    const float* __restrict__ b_fc,
           float* __restrict__ out, int N)
{
    __shared__ __align__(16) float sWdown[H_IN * FP];
    __shared__ __align__(16) float sWd[F * FP];
    __shared__ __align__(16) float sW1T[DH * FP];  // transposed diff1: [m][j]
    __shared__ __align__(16) float sW2[DH];
    __shared__ __align__(16) float sB1[DH];
    __shared__ __align__(16) float sBdown[FP];
    __shared__ __align__(16) float sBdrift[FP];
    __shared__ __align__(16) float sWfc[2 * F];    // [k*2+c]
    __shared__ uint32_t sK0[64], sK1[64];

    const int tid = threadIdx.x;

    for (int idx = tid; idx < H_IN * FP; idx += blockDim.x) {
        int h = idx / FP, k = idx - h * FP;
        sWdown[idx] = (k < F) ? W_down[h * F + k] : 0.0f;
    }
    for (int idx = tid; idx < F * FP; idx += blockDim.x) {
        int j = idx / FP, k = idx - j * FP;
        sWd[idx] = (k < F) ? W_drift[j * F + k] : 0.0f;
    }
    for (int idx = tid; idx < DH * FP; idx += blockDim.x) {
        int m = idx / FP, j = idx - m * FP;
        sW1T[idx] = (j < F) ? W_diff1[j * DH + m] : 0.0f;
    }
    for (int idx = tid; idx < DH; idx += blockDim.x) {
        sW2[idx] = W_diff2[idx];
        sB1[idx] = b_diff1[idx];
        sWfc[idx] = W_fc[idx];
    }
    for (int idx = tid; idx < FP; idx += blockDim.x) {
        sBdown[idx]  = (idx < F) ? b_down[idx]  : 0.0f;
        sBdrift[idx] = (idx < F) ? b_drift[idx] : 0.0f;
    }
    // per-step fold_in keys: threefry((0,42), (0,i))
    if (tid < 64) {
        uint32_t a, b;
        threefry2x32(0u, 42u, 0u, (uint32_t)tid, a, b);
        sK0[tid] = a; sK1[tid] = b;
    }
    __syncthreads();

    const uint32_t t = blockIdx.x * blockDim.x + tid;   // one token per thread
    if (t >= (uint32_t)N) return;
    const uint32_t cbase = t * 50u;                     // flattened sample base

    // ---- state o lives permanently packed: op[q] = (o[2q], o[2q+1]) ----
    uint64_t op[26];
    float coef;
    {
        // downsample: o = x @ W_down + b_down (packed f32x2)
        {
            const ulonglong2* bb = reinterpret_cast<const ulonglong2*>(sBdown);
            #pragma unroll
            for (int q = 0; q < 13; q++) {
                ulonglong2 b2 = bb[q];
                op[2*q] = b2.x; op[2*q+1] = b2.y;
            }
        }
        const float* xp = x + (size_t)t * H_IN;
        #pragma unroll
        for (int h = 0; h < H_IN; h++) {
            float xv = __ldg(xp + h);
            uint64_t xvv = pack2(xv, xv);
            const ulonglong2* wrow = reinterpret_cast<const ulonglong2*>(&sWdown[h * FP]);
            #pragma unroll
            for (int q = 0; q < 13; q++) {
                ulonglong2 w = wrow[q];
                ffma2(op[2*q],   xvv, w.x);
                ffma2(op[2*q+1], xvv, w.y);
            }
        }

        // diffusion net at t=0: coef = SIGMA*sigmoid(relu(o@W1+b1)@W2+b2)*sqrt(dt)
        float ds = __ldg(b_diff2);
        #pragma unroll 4
        for (int m = 0; m < DH; m++) {
            uint64_t sp = pack2(sB1[m], 0.0f);
            const ulonglong2* wrow = reinterpret_cast<const ulonglong2*>(&sW1T[m * FP]);
            #pragma unroll
            for (int q = 0; q < 13; q++) {
                ulonglong2 w = wrow[q];
                ffma2(sp, op[2*q],   w.x);
                ffma2(sp, op[2*q+1], w.y);
            }
            float2 sv = unpack2(sp);
            float s = sv.x + sv.y;
            ds = fmaf(fmaxf(s, 0.0f), sW2[m], ds);
        }
        coef = SIG * (1.0f / (1.0f + expf(-ds))) * SQDT;
    }

    const uint64_t DT2 = pack2(DT, DT);
    const float coefs = coef * 1.41421356f;        // fold sqrt(2) into coef
    const uint64_t coef2 = pack2(coefs, coefs);

    // ---- 64 SDE steps ----
    for (int i = 0; i < 64; i++) {
        const uint32_t fk0 = sK0[i], fk1 = sK1[i];
        const uint32_t fk2 = fk0 ^ fk1 ^ 0x1BD11BDAu;
        const uint32_t kb1 = fk2 + 1u, kb2 = fk0 + 2u, kb3 = fk1 + 3u,
                       kb4 = fk2 + 4u, kb5 = fk0 + 5u;
        const uint32_t x1base = cbase + fk1;     // x1_init = (cbase+f) + k1

        // drift pre-activation (packed): accp = o @ W_drift + b_drift
        uint64_t accp[26];
        {
            const ulonglong2* bb = reinterpret_cast<const ulonglong2*>(sBdrift);
            #pragma unroll
            for (int q = 0; q < 13; q++) {
                ulonglong2 b2 = bb[q];
                accp[2*q] = b2.x; accp[2*q+1] = b2.y;
            }
        }
        #pragma unroll 5
        for (int jq = 0; jq < 25; jq++) {           // feature pair (2jq, 2jq+1)
            float2 ov = unpack2(op[jq]);
            uint64_t o0 = pack2(ov.x, ov.x);
            uint64_t o1 = pack2(ov.y, ov.y);
            const ulonglong2* w0 = reinterpret_cast<const ulonglong2*>(&sWd[(2*jq)   * FP]);
            const ulonglong2* w1 = reinterpret_cast<const ulonglong2*>(&sWd[(2*jq+1) * FP]);
            #pragma unroll
            for (int q = 0; q < 13; q++) {
                ulonglong2 wa = w0[q];
                ulonglong2 wb = w1[q];
                ffma2(accp[2*q],   o0, wa.x);
                ffma2(accp[2*q+1], o0, wa.y);
                ffma2(accp[2*q],   o1, wb.x);
                ffma2(accp[2*q+1], o1, wb.y);
            }
        }

        // noise + packed update: o += relu(acc)*DT + coef'*z'
        #pragma unroll 5
        for (int q = 0; q < 25; q++) {
            uint32_t b0 = tf_bits(fk0, fk1, fk2, kb1, kb2, kb3, kb4, kb5,
                                  x1base + (uint32_t)(2*q));
            uint32_t b1 = tf_bits(fk0, fk1, fk2, kb1, kb2, kb3, kb4, kb5,
                                  x1base + (uint32_t)(2*q) + 1u);
            float z0 = bits_to_normal_noscale(b0);
            float z1 = bits_to_normal_noscale(b1);
            float2 a = unpack2(accp[q]);
            uint64_t ap = pack2(fmaxf(a.x, 0.0f), fmaxf(a.y, 0.0f));
            ffma2(op[q], ap, DT2);
            uint64_t zp = pack2(z0, z1);
            ffma2(op[q], zp, coef2);
        }
    }

    // ---- head: final = relu(o) @ W_fc + b_fc; mu, softplus(sigma)+1e-3 ----
    float mu = __ldg(b_fc + 0);
    float sg = __ldg(b_fc + 1);
    #pragma unroll
    for (int q = 0; q < 25; q++) {
        float2 ov = unpack2(op[q]);
        float r0 = fmaxf(ov.x, 0.0f);
        float r1 = fmaxf(ov.y, 0.0f);
        mu = fmaf(r0, sWfc[4*q],     mu);
        sg = fmaf(r0, sWfc[4*q + 1], sg);
        mu = fmaf(r1, sWfc[4*q + 2], mu);
        sg = fmaf(r1, sWfc[4*q + 3], sg);
    }
    float sigma = fmaxf(sg, 0.0f) + log1pf(expf(-fabsf(sg))) + 0.001f;

    out[t] = mu;
    out[(size_t)N + t] = sigma;
}

extern "C" void kernel_launch(void* const* d_in, const int* in_sizes, int n_in,
                              void* d_out, int out_size)
{
    const float* x       = (const float*)d_in[0];
    const float* W_down  = (const float*)d_in[1];
    const float* b_down  = (const float*)d_in[2];
    const float* W_drift = (const float*)d_in[3];
    const float* b_drift = (const float*)d_in[4];
    const float* W_diff1 = (const float*)d_in[5];
    const float* b_diff1 = (const float*)d_in[6];
    const float* W_diff2 = (const float*)d_in[7];
    const float* b_diff2 = (const float*)d_in[8];
    const float* W_fc    = (const float*)d_in[9];
    const float* b_fc    = (const float*)d_in[10];

    int N = in_sizes[0] / H_IN;          // number of tokens (B*L)
    int threads = 128;
    int blocks = (N + threads - 1) / threads;

    sde_kernel<<<blocks, threads>>>(x, W_down, b_down, W_drift, b_drift,
                                    W_diff1, b_diff1, W_diff2, b_diff2,
                                    W_fc, b_fc, (float*)d_out, N);
}

// round 17
// speedup vs baseline: 1.6120x; 1.0445x over previous
#include <cuda_runtime.h>
#include <cstdint>
#include <math.h>

#define H_IN    24
#define F       50
#define FP      52      // padded feature stride (52*4=208 bytes, 16B aligned)
#define DH      100
#define DT      0.0625f
#define SQDT    0.25f
#define SIG     5.0f

// ---------------- packed f32x2 helpers (Blackwell FFMA2 path) ----------------
__device__ __forceinline__ uint64_t pack2(float lo, float hi) {
    uint64_t r;
    asm("mov.b64 %0, {%1, %2};" : "=l"(r) : "f"(lo), "f"(hi));
    return r;
}
__device__ __forceinline__ float2 unpack2(uint64_t v) {
    float2 r;
    asm("mov.b64 {%0, %1}, %2;" : "=f"(r.x), "=f"(r.y) : "l"(v));
    return r;
}
__device__ __forceinline__ void ffma2(uint64_t& d, uint64_t a, uint64_t b) {
    asm("fma.rn.f32x2 %0, %1, %2, %0;" : "+l"(d) : "l"(a), "l"(b));
}

__device__ __forceinline__ float fast_sqrtf(float x) {
    float r;
    asm("sqrt.approx.f32 %0, %1;" : "=f"(r) : "f"(x));
    return r;
}

// ---------------- Threefry-2x32 (matches JAX) ----------------
__device__ __forceinline__ void tf_round(uint32_t& x0, uint32_t& x1, int r) {
    x0 += x1;
    x1 = __funnelshift_l(x1, x1, r);
    x1 ^= x0;
}

// Full threefry (used for fold_in key derivation)
__device__ __forceinline__ void threefry2x32(uint32_t k0, uint32_t k1,
                                             uint32_t c0, uint32_t c1,
                                             uint32_t& o0, uint32_t& o1) {
    uint32_t k2 = k0 ^ k1 ^ 0x1BD11BDAu;
    uint32_t x0 = c0 + k0, x1 = c1 + k1;
    tf_round(x0,x1,13); tf_round(x0,x1,15); tf_round(x0,x1,26); tf_round(x0,x1, 6);
    x0 += k1; x1 += k2 + 1u;
    tf_round(x0,x1,17); tf_round(x0,x1,29); tf_round(x0,x1,16); tf_round(x0,x1,24);
    x0 += k2; x1 += k0 + 2u;
    tf_round(x0,x1,13); tf_round(x0,x1,15); tf_round(x0,x1,26); tf_round(x0,x1, 6);
    x0 += k0; x1 += k1 + 3u;
    tf_round(x0,x1,17); tf_round(x0,x1,29); tf_round(x0,x1,16); tf_round(x0,x1,24);
    x0 += k1; x1 += k2 + 4u;
    tf_round(x0,x1,13); tf_round(x0,x1,15); tf_round(x0,x1,26); tf_round(x0,x1, 6);
    o0 = x0 + k2;
    o1 = x1 + k0 + 5u;
}

// Partitionable-mode random bits for sample index j (< 2^32):
// counter = (0, j); bits = out0 ^ out1. c0 = 0 folded in (x0 starts at k0).
__device__ __forceinline__ uint32_t tf_bits(uint32_t k0, uint32_t k1, uint32_t k2,
                                            uint32_t kb1, uint32_t kb2, uint32_t kb3,
                                            uint32_t kb4, uint32_t kb5,
                                            uint32_t x1_init) {
    uint32_t x0 = k0;
    uint32_t x1 = x1_init;                       // (cbase + f) + k1
    tf_round(x0,x1,13); tf_round(x0,x1,15); tf_round(x0,x1,26); tf_round(x0,x1, 6);
    x0 += k1; x1 += kb1;
    tf_round(x0,x1,17); tf_round(x0,x1,29); tf_round(x0,x1,16); tf_round(x0,x1,24);
    x0 += k2; x1 += kb2;
    tf_round(x0,x1,13); tf_round(x0,x1,15); tf_round(x0,x1,26); tf_round(x0,x1, 6);
    x0 += k0; x1 += kb3;
    tf_round(x0,x1,17); tf_round(x0,x1,29); tf_round(x0,x1,16); tf_round(x0,x1,24);
    x0 += k1; x1 += kb4;
    tf_round(x0,x1,13); tf_round(x0,x1,15); tf_round(x0,x1,26); tf_round(x0,x1, 6);
    return (x0 + k2) ^ (x1 + kb5);
}

// bits -> erfinv(u)*u normal (sqrt2 folded into coef outside), BRANCHLESS.
// Validated R11/R16 formulation (r exact; single-rounded fma keeps u > -1).
__device__ __forceinline__ float bits_to_normal_noscale(uint32_t bits) {
    float r = __uint_as_float(0x3f800000u | (bits >> 9)) - 1.0f;   // [0,1)
    float u = fmaf(r, 2.0f, -0.99999994f);
    float w = -__logf((1.0f - u) * (1.0f + u));
    float wa = w - 2.5f;
    float pa = 2.81022636e-08f;
    pa = fmaf(pa, wa, 3.43273939e-07f);
    pa = fmaf(pa, wa, -3.5233877e-06f);
    pa = fmaf(pa, wa, -4.39150654e-06f);
    pa = fmaf(pa, wa, 0.00021858087f);
    pa = fmaf(pa, wa, -0.00125372503f);
    pa = fmaf(pa, wa, -0.00417768164f);
    pa = fmaf(pa, wa, 0.246640727f);
    pa = fmaf(pa, wa, 1.50140941f);
    float wb = fast_sqrtf(w) - 3.0f;
    float pb = -0.000200214257f;
    pb = fmaf(pb, wb, 0.000100950558f);
    pb = fmaf(pb, wb, 0.00134934322f);
    pb = fmaf(pb, wb, -0.00367342844f);
    pb = fmaf(pb, wb, 0.00573950773f);
    pb = fmaf(pb, wb, -0.0076224613f);
    pb = fmaf(pb, wb, 0.00943887047f);
    pb = fmaf(pb, wb, 1.00167406f);
    pb = fmaf(pb, wb, 2.83297682f);
    float p = (w < 5.0f) ? pa : pb;     // FSEL, no branch
    return p * u;
}

__global__ void __launch_bounds__(128, 3)
sde_kernel(const float* __restrict__ x,
           const float* __restrict__ W_down,  const float* __restrict__ b_down,
           const float* __restrict__ W_drift, const float* __restrict__ b_drift,
           const float* __restrict__ W_diff1, const float* __restrict__ b_diff1,
           const float* __restrict__ W_diff2, const float* __restrict__ b_diff2,
           const float* __restrict__ W_fc,    const float* __restrict__ b_fc,
           float* __restrict__ out, int N)
{
    __shared__ __align__(16) float sWdown[H_IN * FP];
    __shared__ __align__(16) float sWd[F * FP];
    __shared__ __align__(16) float sW2[DH];
    __shared__ __align__(16) float sB1[DH];
    __shared__ __align__(16) float sBdown[FP];
    __shared__ __align__(16) float sBdrift[FP];
    __shared__ __align__(16) float sWfc[2 * F];
    __shared__ uint32_t sK0[64], sK1[64];
    // dynamic: prologue uses it as sW1T (20.8KB); main loop as o state (51.2KB)
    extern __shared__ __align__(16) char dynS[];
    float* sW1T = reinterpret_cast<float*>(dynS);                    // [DH][FP]
    unsigned long long* oS = reinterpret_cast<unsigned long long*>(dynS); // [2*25][128]

    const int tid = threadIdx.x;

    for (int idx = tid; idx < H_IN * FP; idx += blockDim.x) {
        int h = idx / FP, k = idx - h * FP;
        sWdown[idx] = (k < F) ? W_down[h * F + k] : 0.0f;
    }
    for (int idx = tid; idx < F * FP; idx += blockDim.x) {
        int j = idx / FP, k = idx - j * FP;
        sWd[idx] = (k < F) ? W_drift[j * F + k] : 0.0f;
    }
    for (int idx = tid; idx < DH * FP; idx += blockDim.x) {
        int m = idx / FP, j = idx - m * FP;
        sW1T[idx] = (j < F) ? W_diff1[j * DH + m] : 0.0f;
    }
    for (int idx = tid; idx < DH; idx += blockDim.x) {
        sW2[idx] = W_diff2[idx];
        sB1[idx] = b_diff1[idx];
        sWfc[idx] = W_fc[idx];
    }
    for (int idx = tid; idx < FP; idx += blockDim.x) {
        sBdown[idx]  = (idx < F) ? b_down[idx]  : 0.0f;
        sBdrift[idx] = (idx < F) ? b_drift[idx] : 0.0f;
    }
    if (tid < 64) {
        uint32_t a, b;
        threefry2x32(0u, 42u, 0u, (uint32_t)tid, a, b);
        sK0[tid] = a; sK1[tid] = b;
    }
    __syncthreads();

    const uint32_t t0 = blockIdx.x * 256u + (uint32_t)tid;   // token A
    const uint32_t t1 = t0 + 128u;                           // token B
    const uint32_t tBld = (t1 < (uint32_t)N) ? t1 : (uint32_t)(N - 1); // safe load idx

    // ---- prologue per token: downsample + diffusion coef (op in regs) ----
    uint64_t opA[26], opB[26];
    float coefA, coefB;
    {
        auto prologue = [&](uint32_t tok, uint64_t* op, float& coef) {
            {
                const ulonglong2* bb = reinterpret_cast<const ulonglong2*>(sBdown);
                #pragma unroll
                for (int q = 0; q < 13; q++) {
                    ulonglong2 b2 = bb[q];
                    op[2*q] = b2.x; op[2*q+1] = b2.y;
                }
            }
            const float* xp = x + (size_t)tok * H_IN;
            #pragma unroll
            for (int h = 0; h < H_IN; h++) {
                float xv = __ldg(xp + h);
                uint64_t xvv = pack2(xv, xv);
                const ulonglong2* wrow = reinterpret_cast<const ulonglong2*>(&sWdown[h * FP]);
                #pragma unroll
                for (int q = 0; q < 13; q++) {
                    ulonglong2 w = wrow[q];
                    ffma2(op[2*q],   xvv, w.x);
                    ffma2(op[2*q+1], xvv, w.y);
                }
            }
            float ds = __ldg(b_diff2);
            #pragma unroll 4
            for (int m = 0; m < DH; m++) {
                uint64_t sp = pack2(sB1[m], 0.0f);
                const ulonglong2* wrow = reinterpret_cast<const ulonglong2*>(&sW1T[m * FP]);
                #pragma unroll
                for (int q = 0; q < 13; q++) {
                    ulonglong2 w = wrow[q];
                    ffma2(sp, op[2*q],   w.x);
                    ffma2(sp, op[2*q+1], w.y);
                }
                float2 sv = unpack2(sp);
                float s = sv.x + sv.y;
                ds = fmaf(fmaxf(s, 0.0f), sW2[m], ds);
            }
            coef = SIG * (1.0f / (1.0f + expf(-ds))) * SQDT * 1.41421356f;
        };
        prologue(t0,   opA, coefA);
        prologue(tBld, opB, coefB);
    }
    __syncthreads();   // everyone done reading sW1T; dynS becomes o storage

    #pragma unroll
    for (int q = 0; q < 25; q++) {
        oS[q * 128 + tid]         = opA[q];
        oS[(25 + q) * 128 + tid]  = opB[q];
    }
    // no sync needed: each thread only touches its own [*, tid] slots

    const uint64_t DT2    = pack2(DT, DT);
    const uint64_t coef2A = pack2(coefA, coefA);
    const uint64_t coef2B = pack2(coefB, coefB);

    const uint32_t cbaseA = t0 * 50u;
    const uint32_t cbaseB = t1 * 50u;   // garbage if OOB, never written back

    // ---- 64 SDE steps: weight loads shared across the 2 tokens ----
    for (int i = 0; i < 64; i++) {
        const uint32_t fk0 = sK0[i], fk1 = sK1[i];
        const uint32_t fk2 = fk0 ^ fk1 ^ 0x1BD11BDAu;
        const uint32_t kb1 = fk2 + 1u, kb2 = fk0 + 2u, kb3 = fk1 + 3u,
                       kb4 = fk2 + 4u, kb5 = fk0 + 5u;
        const uint32_t x1bA = cbaseA + fk1;
        const uint32_t x1bB = cbaseB + fk1;

        uint64_t accA[26], accB[26];
        {
            const ulonglong2* bb = reinterpret_cast<const ulonglong2*>(sBdrift);
            #pragma unroll
            for (int q = 0; q < 13; q++) {
                ulonglong2 b2 = bb[q];
                accA[2*q] = b2.x; accA[2*q+1] = b2.y;
                accB[2*q] = b2.x; accB[2*q+1] = b2.y;
            }
        }
        #pragma unroll 5
        for (int jq = 0; jq < 25; jq++) {
            uint64_t oa = oS[jq * 128 + tid];
            uint64_t ob = oS[(25 + jq) * 128 + tid];
            float2 va = unpack2(oa), vb = unpack2(ob);
            uint64_t a0 = pack2(va.x, va.x), a1 = pack2(va.y, va.y);
            uint64_t b0 = pack2(vb.x, vb.x), b1 = pack2(vb.y, vb.y);
            const ulonglong2* w0 = reinterpret_cast<const ulonglong2*>(&sWd[(2*jq)   * FP]);
            const ulonglong2* w1 = reinterpret_cast<const ulonglong2*>(&sWd[(2*jq+1) * FP]);
            #pragma unroll
            for (int q = 0; q < 13; q++) {
                ulonglong2 wa = w0[q];
                ulonglong2 wb = w1[q];
                ffma2(accA[2*q],   a0, wa.x);
                ffma2(accA[2*q+1], a0, wa.y);
                ffma2(accA[2*q],   a1, wb.x);
                ffma2(accA[2*q+1], a1, wb.y);
                ffma2(accB[2*q],   b0, wa.x);
                ffma2(accB[2*q+1], b0, wa.y);
                ffma2(accB[2*q],   b1, wb.x);
                ffma2(accB[2*q+1], b1, wb.y);
            }
        }

        // noise + update: 4 independent Threefry chains per iteration
        #pragma unroll 2
        for (int q = 0; q < 25; q++) {
            uint32_t bA0 = tf_bits(fk0, fk1, fk2, kb1, kb2, kb3, kb4, kb5,
                                   x1bA + (uint32_t)(2*q));
            uint32_t bA1 = tf_bits(fk0, fk1, fk2, kb1, kb2, kb3, kb4, kb5,
                                   x1bA + (uint32_t)(2*q) + 1u);
            uint32_t bB0 = tf_bits(fk0, fk1, fk2, kb1, kb2, kb3, kb4, kb5,
                                   x1bB + (uint32_t)(2*q));
            uint32_t bB1 = tf_bits(fk0, fk1, fk2, kb1, kb2, kb3, kb4, kb5,
                                   x1bB + (uint32_t)(2*q) + 1u);
            float zA0 = bits_to_normal_noscale(bA0);
            float zA1 = bits_to_normal_noscale(bA1);
            float zB0 = bits_to_normal_noscale(bB0);
            float zB1 = bits_to_normal_noscale(bB1);

            float2 aA = unpack2(accA[q]);
            uint64_t nA = oS[q * 128 + tid];
            ffma2(nA, pack2(fmaxf(aA.x, 0.0f), fmaxf(aA.y, 0.0f)), DT2);
            ffma2(nA, pack2(zA0, zA1), coef2A);
            oS[q * 128 + tid] = nA;

            float2 aB = unpack2(accB[q]);
            uint64_t nB = oS[(25 + q) * 128 + tid];
            ffma2(nB, pack2(fmaxf(aB.x, 0.0f), fmaxf(aB.y, 0.0f)), DT2);
            ffma2(nB, pack2(zB0, zB1), coef2B);
            oS[(25 + q) * 128 + tid] = nB;
        }
    }

    // ---- head for both tokens ----
    {
        float muA = __ldg(b_fc + 0), sgA = __ldg(b_fc + 1);
        float muB = muA, sgB = sgA;
        #pragma unroll
        for (int q = 0; q < 25; q++) {
            float2 ovA = unpack2(oS[q * 128 + tid]);
            float2 ovB = unpack2(oS[(25 + q) * 128 + tid]);
            float rA0 = fmaxf(ovA.x, 0.0f), rA1 = fmaxf(ovA.y, 0.0f);
            float rB0 = fmaxf(ovB.x, 0.0f), rB1 = fmaxf(ovB.y, 0.0f);
            muA = fmaf(rA0, sWfc[4*q],     muA);
            sgA = fmaf(rA0, sWfc[4*q + 1], sgA);
            muA = fmaf(rA1, sWfc[4*q + 2], muA);
            sgA = fmaf(rA1, sWfc[4*q + 3], sgA);
            muB = fmaf(rB0, sWfc[4*q],     muB);
            sgB = fmaf(rB0, sWfc[4*q + 1], sgB);
            muB = fmaf(rB1, sWfc[4*q + 2], muB);
            sgB = fmaf(rB1, sWfc[4*q + 3], sgB);
        }
        float siA = fmaxf(sgA, 0.0f) + log1pf(expf(-fabsf(sgA))) + 0.001f;
        float siB = fmaxf(sgB, 0.0f) + log1pf(expf(-fabsf(sgB))) + 0.001f;
        if (t0 < (uint32_t)N) {
            out[t0] = muA;
            out[(size_t)N + t0] = siA;
        }
        if (t1 < (uint32_t)N) {
            out[t1] = muB;
            out[(size_t)N + t1] = siB;
        }
    }
}

extern "C" void kernel_launch(void* const* d_in, const int* in_sizes, int n_in,
                              void* d_out, int out_size)
{
    const float* x       = (const float*)d_in[0];
    const float* W_down  = (const float*)d_in[1];
    const float* b_down  = (const float*)d_in[2];
    const float* W_drift = (const float*)d_in[3];
    const float* b_drift = (const float*)d_in[4];
    const float* W_diff1 = (const float*)d_in[5];
    const float* b_diff1 = (const float*)d_in[6];
    const float* W_diff2 = (const float*)d_in[7];
    const float* b_diff2 = (const float*)d_in[8];
    const float* W_fc    = (const float*)d_in[9];
    const float* b_fc    = (const float*)d_in[10];

    int N = in_sizes[0] / H_IN;              // number of tokens (B*L)
    int threads = 128;
    int blocks = (N + 255) / 256;            // 2 tokens per thread
    size_t dyn_smem = 2 * 25 * 128 * sizeof(unsigned long long);   // 51.2 KB

    // Opt in to static(~17.5KB) + dynamic(51.2KB). Legal during graph capture
    // (attribute set, not a stream op); idempotent; no allocation.
    cudaFuncSetAttribute(sde_kernel, cudaFuncAttributeMaxDynamicSharedMemorySize,
                         (int)dyn_smem);

    sde_kernel<<<blocks, threads, dyn_smem>>>(x, W_down, b_down, W_drift, b_drift,
                                              W_diff1, b_diff1, W_diff2, b_diff2,
                                              W_fc, b_fc, (float*)d_out, N);
}